// round 7
// baseline (speedup 1.0000x reference)
#include <cuda_runtime.h>

#define NLEV 16
#define LOG2_T 19
#define TSIZE (1u << LOG2_T)
#define TMASK (TSIZE - 1u)
#define PRIME_Y 2654435761u
#define PRIME_Z 805459861u

#define CAP   2200000
#define NBINS 32768          // 15-bit Morton key at res 32

typedef unsigned long long ull;

// Static scratch (allocation-free): sorted coords, permutation, histogram.
__device__ float4   g_xs[CAP];
__device__ int      g_perm[CAP];
__device__ unsigned g_hist[NBINS];

// ---------------- sorting pre-pass ----------------

__device__ __forceinline__ unsigned morton_key(float x0, float x1, float x2) {
    int cx = (int)(x0 * 32.0f); cx = cx < 0 ? 0 : (cx > 31 ? 31 : cx);
    int cy = (int)(x1 * 32.0f); cy = cy < 0 ? 0 : (cy > 31 ? 31 : cy);
    int cz = (int)(x2 * 32.0f); cz = cz < 0 ? 0 : (cz > 31 ? 31 : cz);
    unsigned m = 0;
    #pragma unroll
    for (int d = 0; d < 5; d++) {
        m |= ((unsigned)(cx >> d) & 1u) << (3 * d + 0);
        m |= ((unsigned)(cy >> d) & 1u) << (3 * d + 1);
        m |= ((unsigned)(cz >> d) & 1u) << (3 * d + 2);
    }
    return m;
}

__global__ void zero_hist_k() {
    int i = blockIdx.x * blockDim.x + threadIdx.x;
    if (i < NBINS) g_hist[i] = 0u;
}

__global__ void hist_k(const float* __restrict__ x, int N) {
    int i = blockIdx.x * blockDim.x + threadIdx.x;
    if (i >= N) return;
    float x0 = x[3 * i + 0] * 0.5f + 0.5f;
    float x1 = x[3 * i + 1] * 0.5f + 0.5f;
    float x2 = x[3 * i + 2] * 0.5f + 0.5f;
    atomicAdd(&g_hist[morton_key(x0, x1, x2)], 1u);
}

// Single-block exclusive scan of g_hist (32768 = 1024 threads x 32 each).
// Overwrites g_hist with the exclusive prefix (scatter base counters).
__global__ void scan_k() {
    __shared__ unsigned sm[1024];
    const int t = threadIdx.x;
    unsigned vals[32];
    unsigned s = 0;
    #pragma unroll
    for (int k = 0; k < 32; k++) { vals[k] = g_hist[t * 32 + k]; s += vals[k]; }
    sm[t] = s;
    __syncthreads();
    for (int off = 1; off < 1024; off <<= 1) {
        unsigned v = (t >= off) ? sm[t - off] : 0u;
        __syncthreads();
        sm[t] += v;
        __syncthreads();
    }
    unsigned run = sm[t] - s;            // exclusive prefix of this chunk
    #pragma unroll
    for (int k = 0; k < 32; k++) { g_hist[t * 32 + k] = run; run += vals[k]; }
}

__global__ void scatter_k(const float* __restrict__ x, int N) {
    int i = blockIdx.x * blockDim.x + threadIdx.x;
    if (i >= N) return;
    float x0 = x[3 * i + 0] * 0.5f + 0.5f;
    float x1 = x[3 * i + 1] * 0.5f + 0.5f;
    float x2 = x[3 * i + 2] * 0.5f + 0.5f;
    unsigned key = morton_key(x0, x1, x2);
    unsigned slot = atomicAdd(&g_hist[key], 1u);
    // streaming stores: staging is read-once, keep it out of L2's table set
    __stcs(&g_xs[slot], make_float4(x0, x1, x2, 0.0f));
    __stcs(&g_perm[slot], i);
}

// ---------------- main fused kernel ----------------

// packed fp32x2 FMA (full-precision fp32, 2 lanes per instruction)
__device__ __forceinline__ ull fma2u(ull a, ull b, ull c) {
    ull d;
    asm("fma.rn.f32x2 %0, %1, %2, %3;" : "=l"(d) : "l"(a), "l"(b), "l"(c));
    return d;
}
__device__ __forceinline__ ull pack2(float lo, float hi) {
    ull r;
    asm("mov.b64 %0, {%1, %2};" : "=l"(r) : "f"(lo), "f"(hi));
    return r;
}
__device__ __forceinline__ void unpack2(ull v, float& lo, float& hi) {
    asm("mov.b64 {%0, %1}, %2;" : "=f"(lo), "=f"(hi) : "l"(v));
}

__global__ __launch_bounds__(256, 2)
void hashgrid_mlp_kernel(const float2* __restrict__ tables,
                         const float*  __restrict__ resolutions,
                         const float*  __restrict__ W1, const float* __restrict__ b1,
                         const float*  __restrict__ W2, const float* __restrict__ b2,
                         const float*  __restrict__ W3, const float* __restrict__ b3,
                         float* __restrict__ out, int N)
{
    __shared__ __align__(16) float sW1[32 * 64];
    __shared__ __align__(16) float sW2[64 * 64];
    __shared__ __align__(16) float sB1[64];
    __shared__ __align__(16) float sB2[64];
    __shared__ __align__(16) float sW3[64];
    __shared__ __align__(16) float sRes[16];
    __shared__ float sB3;

    const int tid = threadIdx.x;
    for (int k = tid; k < 32 * 64; k += blockDim.x) sW1[k] = W1[k];
    for (int k = tid; k < 64 * 64; k += blockDim.x) sW2[k] = W2[k];
    if (tid < 64) { sB1[tid] = b1[tid]; sB2[tid] = b2[tid]; sW3[tid] = W3[tid]; }
    if (tid < 16) sRes[tid] = resolutions[tid];
    if (tid == 0) sB3 = b3[0];
    __syncthreads();

    const int i = blockIdx.x * blockDim.x + tid;
    if (i >= N) return;

    const float4 xs = __ldcs(&g_xs[i]);  // sorted, [0,1]; read-once streaming
    const float x0 = xs.x, x1 = xs.y, x2 = xs.z;

    // h1 accumulators: 32 packed f32x2 = neurons (2j, 2j+1); init with bias
    ull h1u[32];
    #pragma unroll
    for (int j = 0; j < 32; j++) h1u[j] = ((const ull*)sB1)[j];

    // two-stage pipeline for the per-level gathers.
    // tbuf slots (2j, 2j+1) hold the x-corner PAIR for (y,z)-combo j.
    // mbuf bit j: 1 if slot order is (cx+1, cx) instead of (cx, cx+1).
    float2   tbuf[2][8];
    float    wbuf[2][3];
    unsigned mbuf[2];

    // fineL: true -> working set >> L1, bypass L1 allocation (ld.global.cg)
    auto issue = [&](int L, bool fineL, float2* tb, float* wb, unsigned& mb) {
        const float res = sRes[L];
        const float px = x0 * res, py = x1 * res, pz = x2 * res;
        const float fx = floorf(px), fy = floorf(py), fz = floorf(pz);
        wb[0] = px - fx; wb[1] = py - fy; wb[2] = pz - fz;
        const unsigned cx = (unsigned)fx, cy = (unsigned)fy, cz = (unsigned)fz;
        const unsigned hy0 = cy * PRIME_Y, hy1 = hy0 + PRIME_Y;
        const unsigned hz0 = cz * PRIME_Z, hz1 = hz0 + PRIME_Z;
        unsigned rr[4];
        rr[0] = hy0 ^ hz0; rr[1] = hy1 ^ hz0; rr[2] = hy0 ^ hz1; rr[3] = hy1 ^ hz1;
        const float2* __restrict__ base = tables + (size_t)L * TSIZE;
        unsigned m = 0;
        if (!(cx & 1u)) {
            // cx even: idx(cx+1) = idx(cx) ^ 1 -> one aligned float4 per (y,z) combo
            #pragma unroll
            for (int j = 0; j < 4; j++) {
                const unsigned i0 = (cx ^ rr[j]) & TMASK;
                m |= (i0 & 1u) << j;            // slot order swapped iff idx(cx) is odd
                const float4* p = (const float4*)(base + (i0 & ~1u));
                const float4 v = fineL ? __ldcg(p) : __ldg(p);
                tb[2 * j]     = make_float2(v.x, v.y);
                tb[2 * j + 1] = make_float2(v.z, v.w);
            }
        } else {
            #pragma unroll
            for (int j = 0; j < 4; j++) {
                const unsigned i0 = (cx        ^ rr[j]) & TMASK;
                const unsigned i1 = ((cx + 1u) ^ rr[j]) & TMASK;
                tb[2 * j]     = fineL ? __ldcg(base + i0) : __ldg(base + i0);
                tb[2 * j + 1] = fineL ? __ldcg(base + i1) : __ldg(base + i1);
            }
        }
        mb = m;
    };

    issue(0, false, tbuf[0], wbuf[0], mbuf[0]);

    #pragma unroll
    for (int L = 0; L < NLEV; L++) {
        const int cur = L & 1;
        if (L < NLEV - 1)
            issue(L + 1, (L + 1) >= 7, tbuf[cur ^ 1], wbuf[cur ^ 1], mbuf[cur ^ 1]);

        // trilinear interpolation for level L (consumes prefetched tbuf[cur])
        const float wx1 = wbuf[cur][0], wy1 = wbuf[cur][1], wz1 = wbuf[cur][2];
        const float wx0 = 1.0f - wx1, wy0 = 1.0f - wy1, wz0 = 1.0f - wz1;
        float wyz[4];
        wyz[0] = wy0 * wz0; wyz[1] = wy1 * wz0; wyz[2] = wy0 * wz1; wyz[3] = wy1 * wz1;
        const float2* t = tbuf[cur];
        const unsigned m = mbuf[cur];
        float f0 = 0.0f, f1 = 0.0f;
        #pragma unroll
        for (int j = 0; j < 4; j++) {
            const bool  s  = (m >> j) & 1u;
            const float wl = s ? wx1 : wx0;      // weight for slot 2j
            const float wh = s ? wx0 : wx1;      // weight for slot 2j+1
            const float cl = wl * wyz[j], ch = wh * wyz[j];
            f0 += cl * t[2 * j].x + ch * t[2 * j + 1].x;
            f1 += cl * t[2 * j].y + ch * t[2 * j + 1].y;
        }

        // stream the 2 features of this level straight into layer-1 accumulators
        const ull a0 = pack2(f0, f0);
        const ull a1 = pack2(f1, f1);
        const ulonglong2* __restrict__ wv =
            (const ulonglong2*)(sW1 + (2 * L) * 64);   // row 2L then row 2L+1
        #pragma unroll
        for (int q = 0; q < 16; q++) {
            ulonglong2 Wp = wv[q];                     // LDS.128, broadcast
            h1u[2 * q]     = fma2u(a0, Wp.x, h1u[2 * q]);
            h1u[2 * q + 1] = fma2u(a0, Wp.y, h1u[2 * q + 1]);
        }
        #pragma unroll
        for (int q = 0; q < 16; q++) {
            ulonglong2 Wp = wv[16 + q];
            h1u[2 * q]     = fma2u(a1, Wp.x, h1u[2 * q]);
            h1u[2 * q + 1] = fma2u(a1, Wp.y, h1u[2 * q + 1]);
        }
    }

    // ---- layer 2 (relu(h1) @ W2 + b2) and layer 3 fused, 2 tiles of 32 neurons ----
    float outv = sB3;
    #pragma unroll
    for (int tile = 0; tile < 2; tile++) {
        ull acc[16];
        #pragma unroll
        for (int m = 0; m < 16; m++)
            acc[m] = ((const ull*)(sB2 + tile * 32))[m];

        #pragma unroll
        for (int k = 0; k < 64; k++) {
            float lo, hi;
            unpack2(h1u[k >> 1], lo, hi);
            float v = (k & 1) ? hi : lo;
            v = fmaxf(v, 0.0f);                        // relu on layer-1 activation
            const ull r = pack2(v, v);
            const ulonglong2* __restrict__ wrow =
                (const ulonglong2*)(sW2 + k * 64 + tile * 32);
            #pragma unroll
            for (int m = 0; m < 8; m++) {
                ulonglong2 Wp = wrow[m];               // LDS.128, broadcast
                acc[2 * m]     = fma2u(r, Wp.x, acc[2 * m]);
                acc[2 * m + 1] = fma2u(r, Wp.y, acc[2 * m + 1]);
            }
        }
        #pragma unroll
        for (int m = 0; m < 16; m++) {
            float e0, e1;
            unpack2(acc[m], e0, e1);
            outv += fmaxf(e0, 0.0f) * sW3[tile * 32 + 2 * m]
                  + fmaxf(e1, 0.0f) * sW3[tile * 32 + 2 * m + 1];
        }
    }

    __stcs(&out[__ldcs(&g_perm[i])], outv);   // route back to original order
}

extern "C" void kernel_launch(void* const* d_in, const int* in_sizes, int n_in,
                              void* d_out, int out_size)
{
    const float*  x    = (const float*) d_in[0];
    const float2* tabs = (const float2*)d_in[1];
    const float*  res  = (const float*) d_in[2];
    const float*  W1   = (const float*) d_in[3];
    const float*  b1   = (const float*) d_in[4];
    const float*  W2   = (const float*) d_in[5];
    const float*  b2   = (const float*) d_in[6];
    const float*  W3   = (const float*) d_in[7];
    const float*  b3   = (const float*) d_in[8];

    const int N = in_sizes[0] / 3;
    const int threads = 256;
    const int blocks = (N + threads - 1) / threads;

    // spatial binning presort (all graph-capturable kernel launches)
    zero_hist_k<<<(NBINS + 255) / 256, 256>>>();
    hist_k<<<blocks, threads>>>(x, N);
    scan_k<<<1, 1024>>>();
    scatter_k<<<blocks, threads>>>(x, N);

    hashgrid_mlp_kernel<<<blocks, threads>>>(tabs, res, W1, b1, W2, b2, W3, b3,
                                             (float*)d_out, N);
}

// round 8
// speedup vs baseline: 1.0075x; 1.0075x over previous
#include <cuda_runtime.h>

#define NLEV 16
#define LOG2_T 19
#define TSIZE (1u << LOG2_T)
#define TMASK (TSIZE - 1u)
#define PRIME_Y 2654435761u
#define PRIME_Z 805459861u

#define CAP   2200000
#define NBINS 32768          // 15-bit Morton key at res 32

typedef unsigned long long ull;

// Static scratch (allocation-free): sorted coords, permutation, histogram.
__device__ float4   g_xs[CAP];
__device__ int      g_perm[CAP];
__device__ unsigned g_hist[NBINS];

// ---------------- sorting pre-pass ----------------

__device__ __forceinline__ unsigned morton_key(float x0, float x1, float x2) {
    int cx = (int)(x0 * 32.0f); cx = cx < 0 ? 0 : (cx > 31 ? 31 : cx);
    int cy = (int)(x1 * 32.0f); cy = cy < 0 ? 0 : (cy > 31 ? 31 : cy);
    int cz = (int)(x2 * 32.0f); cz = cz < 0 ? 0 : (cz > 31 ? 31 : cz);
    unsigned m = 0;
    #pragma unroll
    for (int d = 0; d < 5; d++) {
        m |= ((unsigned)(cx >> d) & 1u) << (3 * d + 0);
        m |= ((unsigned)(cy >> d) & 1u) << (3 * d + 1);
        m |= ((unsigned)(cz >> d) & 1u) << (3 * d + 2);
    }
    return m;
}

__global__ void zero_hist_k() {
    int i = blockIdx.x * blockDim.x + threadIdx.x;
    if (i < NBINS) g_hist[i] = 0u;
}

__global__ void hist_k(const float* __restrict__ x, int N) {
    int i = blockIdx.x * blockDim.x + threadIdx.x;
    if (i >= N) return;
    float x0 = x[3 * i + 0] * 0.5f + 0.5f;
    float x1 = x[3 * i + 1] * 0.5f + 0.5f;
    float x2 = x[3 * i + 2] * 0.5f + 0.5f;
    atomicAdd(&g_hist[morton_key(x0, x1, x2)], 1u);
}

// Single-block exclusive scan of g_hist (32768 = 1024 threads x 32 each).
// Overwrites g_hist with the exclusive prefix (scatter base counters).
__global__ void scan_k() {
    __shared__ unsigned sm[1024];
    const int t = threadIdx.x;
    unsigned vals[32];
    unsigned s = 0;
    #pragma unroll
    for (int k = 0; k < 32; k++) { vals[k] = g_hist[t * 32 + k]; s += vals[k]; }
    sm[t] = s;
    __syncthreads();
    for (int off = 1; off < 1024; off <<= 1) {
        unsigned v = (t >= off) ? sm[t - off] : 0u;
        __syncthreads();
        sm[t] += v;
        __syncthreads();
    }
    unsigned run = sm[t] - s;            // exclusive prefix of this chunk
    #pragma unroll
    for (int k = 0; k < 32; k++) { g_hist[t * 32 + k] = run; run += vals[k]; }
}

__global__ void scatter_k(const float* __restrict__ x, int N) {
    int i = blockIdx.x * blockDim.x + threadIdx.x;
    if (i >= N) return;
    float x0 = x[3 * i + 0] * 0.5f + 0.5f;
    float x1 = x[3 * i + 1] * 0.5f + 0.5f;
    float x2 = x[3 * i + 2] * 0.5f + 0.5f;
    unsigned key = morton_key(x0, x1, x2);
    unsigned slot = atomicAdd(&g_hist[key], 1u);
    g_xs[slot] = make_float4(x0, x1, x2, 0.0f);
    g_perm[slot] = i;
}

// ---------------- main fused kernel ----------------

// packed fp32x2 FMA (full-precision fp32, 2 lanes per instruction)
__device__ __forceinline__ ull fma2u(ull a, ull b, ull c) {
    ull d;
    asm("fma.rn.f32x2 %0, %1, %2, %3;" : "=l"(d) : "l"(a), "l"(b), "l"(c));
    return d;
}
__device__ __forceinline__ ull pack2(float lo, float hi) {
    ull r;
    asm("mov.b64 %0, {%1, %2};" : "=l"(r) : "f"(lo), "f"(hi));
    return r;
}
__device__ __forceinline__ void unpack2(ull v, float& lo, float& hi) {
    asm("mov.b64 {%0, %1}, %2;" : "=f"(lo), "=f"(hi) : "l"(v));
}

__global__ __launch_bounds__(256, 2)
void hashgrid_mlp_kernel(const float2* __restrict__ tables,
                         const float*  __restrict__ resolutions,
                         const float*  __restrict__ W1, const float* __restrict__ b1,
                         const float*  __restrict__ W2, const float* __restrict__ b2,
                         const float*  __restrict__ W3, const float* __restrict__ b3,
                         float* __restrict__ out, int N)
{
    __shared__ __align__(16) float sW1[32 * 64];
    __shared__ __align__(16) float sW2[64 * 64];
    __shared__ __align__(16) float sB1[64];
    __shared__ __align__(16) float sB2[64];
    __shared__ __align__(16) float sW3[64];
    __shared__ __align__(16) float sRes[16];
    __shared__ float sB3;

    const int tid = threadIdx.x;
    for (int k = tid; k < 32 * 64; k += blockDim.x) sW1[k] = W1[k];
    for (int k = tid; k < 64 * 64; k += blockDim.x) sW2[k] = W2[k];
    if (tid < 64) { sB1[tid] = b1[tid]; sB2[tid] = b2[tid]; sW3[tid] = W3[tid]; }
    if (tid < 16) sRes[tid] = resolutions[tid];
    if (tid == 0) sB3 = b3[0];
    __syncthreads();

    const int i = blockIdx.x * blockDim.x + tid;
    if (i >= N) return;

    const float4 xs = g_xs[i];           // sorted, already mapped to [0,1]
    const float x0 = xs.x, x1 = xs.y, x2 = xs.z;

    // h1 accumulators: 32 packed f32x2 = neurons (2j, 2j+1); init with bias
    ull h1u[32];
    #pragma unroll
    for (int j = 0; j < 32; j++) h1u[j] = ((const ull*)sB1)[j];

    // two-stage pipeline for the per-level gathers.
    // tbuf slots (2j, 2j+1) hold the x-corner PAIR for (y,z)-combo j.
    // mbuf bit j: 1 if slot order is (cx+1, cx) instead of (cx, cx+1).
    float2   tbuf[2][8];
    float    wbuf[2][3];
    unsigned mbuf[2];

    // fineL: CTA-level footprint >> L1 -> bypass L1 allocation (ld.global.cg).
    // Post-sort, levels up to res~128 keep an L1-resident footprint: keep .ca there.
    auto issue = [&](int L, bool fineL, float2* tb, float* wb, unsigned& mb) {
        const float res = sRes[L];
        const float px = x0 * res, py = x1 * res, pz = x2 * res;
        const float fx = floorf(px), fy = floorf(py), fz = floorf(pz);
        wb[0] = px - fx; wb[1] = py - fy; wb[2] = pz - fz;
        const unsigned cx = (unsigned)fx, cy = (unsigned)fy, cz = (unsigned)fz;
        const unsigned hy0 = cy * PRIME_Y, hy1 = hy0 + PRIME_Y;
        const unsigned hz0 = cz * PRIME_Z, hz1 = hz0 + PRIME_Z;
        unsigned rr[4];
        rr[0] = hy0 ^ hz0; rr[1] = hy1 ^ hz0; rr[2] = hy0 ^ hz1; rr[3] = hy1 ^ hz1;
        const float2* __restrict__ base = tables + (size_t)L * TSIZE;
        unsigned m = 0;
        if (!(cx & 1u)) {
            // cx even: idx(cx+1) = idx(cx) ^ 1 -> one aligned float4 per (y,z) combo
            #pragma unroll
            for (int j = 0; j < 4; j++) {
                const unsigned i0 = (cx ^ rr[j]) & TMASK;
                m |= (i0 & 1u) << j;            // slot order swapped iff idx(cx) is odd
                const float4* p = (const float4*)(base + (i0 & ~1u));
                const float4 v = fineL ? __ldcg(p) : __ldg(p);
                tb[2 * j]     = make_float2(v.x, v.y);
                tb[2 * j + 1] = make_float2(v.z, v.w);
            }
        } else {
            #pragma unroll
            for (int j = 0; j < 4; j++) {
                const unsigned i0 = (cx        ^ rr[j]) & TMASK;
                const unsigned i1 = ((cx + 1u) ^ rr[j]) & TMASK;
                tb[2 * j]     = fineL ? __ldcg(base + i0) : __ldg(base + i0);
                tb[2 * j + 1] = fineL ? __ldcg(base + i1) : __ldg(base + i1);
            }
        }
        mb = m;
    };

    issue(0, false, tbuf[0], wbuf[0], mbuf[0]);

    #pragma unroll
    for (int L = 0; L < NLEV; L++) {
        const int cur = L & 1;
        if (L < NLEV - 1)
            issue(L + 1, (L + 1) >= 10, tbuf[cur ^ 1], wbuf[cur ^ 1], mbuf[cur ^ 1]);

        // trilinear interpolation for level L (consumes prefetched tbuf[cur])
        const float wx1 = wbuf[cur][0], wy1 = wbuf[cur][1], wz1 = wbuf[cur][2];
        const float wx0 = 1.0f - wx1, wy0 = 1.0f - wy1, wz0 = 1.0f - wz1;
        float wyz[4];
        wyz[0] = wy0 * wz0; wyz[1] = wy1 * wz0; wyz[2] = wy0 * wz1; wyz[3] = wy1 * wz1;
        const float2* t = tbuf[cur];
        const unsigned m = mbuf[cur];
        float f0 = 0.0f, f1 = 0.0f;
        #pragma unroll
        for (int j = 0; j < 4; j++) {
            const bool  s  = (m >> j) & 1u;
            const float wl = s ? wx1 : wx0;      // weight for slot 2j
            const float wh = s ? wx0 : wx1;      // weight for slot 2j+1
            const float cl = wl * wyz[j], ch = wh * wyz[j];
            f0 += cl * t[2 * j].x + ch * t[2 * j + 1].x;
            f1 += cl * t[2 * j].y + ch * t[2 * j + 1].y;
        }

        // stream the 2 features of this level straight into layer-1 accumulators
        const ull a0 = pack2(f0, f0);
        const ull a1 = pack2(f1, f1);
        const ulonglong2* __restrict__ wv =
            (const ulonglong2*)(sW1 + (2 * L) * 64);   // row 2L then row 2L+1
        #pragma unroll
        for (int q = 0; q < 16; q++) {
            ulonglong2 Wp = wv[q];                     // LDS.128, broadcast
            h1u[2 * q]     = fma2u(a0, Wp.x, h1u[2 * q]);
            h1u[2 * q + 1] = fma2u(a0, Wp.y, h1u[2 * q + 1]);
        }
        #pragma unroll
        for (int q = 0; q < 16; q++) {
            ulonglong2 Wp = wv[16 + q];
            h1u[2 * q]     = fma2u(a1, Wp.x, h1u[2 * q]);
            h1u[2 * q + 1] = fma2u(a1, Wp.y, h1u[2 * q + 1]);
        }
    }

    // ---- layer 2 (relu(h1) @ W2 + b2) and layer 3 fused, 2 tiles of 32 neurons ----
    float outv = sB3;
    #pragma unroll
    for (int tile = 0; tile < 2; tile++) {
        ull acc[16];
        #pragma unroll
        for (int m = 0; m < 16; m++)
            acc[m] = ((const ull*)(sB2 + tile * 32))[m];

        #pragma unroll
        for (int k = 0; k < 64; k++) {
            float lo, hi;
            unpack2(h1u[k >> 1], lo, hi);
            float v = (k & 1) ? hi : lo;
            v = fmaxf(v, 0.0f);                        // relu on layer-1 activation
            const ull r = pack2(v, v);
            const ulonglong2* __restrict__ wrow =
                (const ulonglong2*)(sW2 + k * 64 + tile * 32);
            #pragma unroll
            for (int m = 0; m < 8; m++) {
                ulonglong2 Wp = wrow[m];               // LDS.128, broadcast
                acc[2 * m]     = fma2u(r, Wp.x, acc[2 * m]);
                acc[2 * m + 1] = fma2u(r, Wp.y, acc[2 * m + 1]);
            }
        }
        #pragma unroll
        for (int m = 0; m < 16; m++) {
            float e0, e1;
            unpack2(acc[m], e0, e1);
            outv += fmaxf(e0, 0.0f) * sW3[tile * 32 + 2 * m]
                  + fmaxf(e1, 0.0f) * sW3[tile * 32 + 2 * m + 1];
        }
    }

    out[g_perm[i]] = outv;               // route back to original order
}

extern "C" void kernel_launch(void* const* d_in, const int* in_sizes, int n_in,
                              void* d_out, int out_size)
{
    const float*  x    = (const float*) d_in[0];
    const float2* tabs = (const float2*)d_in[1];
    const float*  res  = (const float*) d_in[2];
    const float*  W1   = (const float*) d_in[3];
    const float*  b1   = (const float*) d_in[4];
    const float*  W2   = (const float*) d_in[5];
    const float*  b2   = (const float*) d_in[6];
    const float*  W3   = (const float*) d_in[7];
    const float*  b3   = (const float*) d_in[8];

    const int N = in_sizes[0] / 3;
    const int threads = 256;
    const int blocks = (N + threads - 1) / threads;

    // spatial binning presort (all graph-capturable kernel launches)
    zero_hist_k<<<(NBINS + 255) / 256, 256>>>();
    hist_k<<<blocks, threads>>>(x, N);
    scan_k<<<1, 1024>>>();
    scatter_k<<<blocks, threads>>>(x, N);

    hashgrid_mlp_kernel<<<blocks, threads>>>(tabs, res, W1, b1, W2, b2, W3, b3,
                                             (float*)d_out, N);
}

// round 9
// speedup vs baseline: 1.0214x; 1.0137x over previous
#include <cuda_runtime.h>

#define NLEV 16
#define LOG2_T 19
#define TSIZE (1u << LOG2_T)
#define TMASK (TSIZE - 1u)
#define PRIME_Y 2654435761u
#define PRIME_Z 805459861u

#define CAP   2200000
#define NBINS 32768          // 15-bit Morton key at res 32

typedef unsigned long long ull;

// Static scratch (allocation-free): sorted coords, permutation, histogram.
__device__ float4   g_xs[CAP];
__device__ int      g_perm[CAP];
__device__ unsigned g_hist[NBINS];

// ---------------- sorting pre-pass ----------------

__device__ __forceinline__ unsigned morton_key(float x0, float x1, float x2) {
    int cx = (int)(x0 * 32.0f); cx = cx < 0 ? 0 : (cx > 31 ? 31 : cx);
    int cy = (int)(x1 * 32.0f); cy = cy < 0 ? 0 : (cy > 31 ? 31 : cy);
    int cz = (int)(x2 * 32.0f); cz = cz < 0 ? 0 : (cz > 31 ? 31 : cz);
    unsigned m = 0;
    #pragma unroll
    for (int d = 0; d < 5; d++) {
        m |= ((unsigned)(cx >> d) & 1u) << (3 * d + 0);
        m |= ((unsigned)(cy >> d) & 1u) << (3 * d + 1);
        m |= ((unsigned)(cz >> d) & 1u) << (3 * d + 2);
    }
    return m;
}

__global__ void zero_hist_k() {
    int i = blockIdx.x * blockDim.x + threadIdx.x;
    if (i < NBINS) g_hist[i] = 0u;
}

__global__ void hist_k(const float* __restrict__ x, int N) {
    int i = blockIdx.x * blockDim.x + threadIdx.x;
    if (i >= N) return;
    float x0 = x[3 * i + 0] * 0.5f + 0.5f;
    float x1 = x[3 * i + 1] * 0.5f + 0.5f;
    float x2 = x[3 * i + 2] * 0.5f + 0.5f;
    atomicAdd(&g_hist[morton_key(x0, x1, x2)], 1u);
}

// Single-block exclusive scan of g_hist (32768 = 1024 threads x 32 each).
__global__ void scan_k() {
    __shared__ unsigned sm[1024];
    const int t = threadIdx.x;
    unsigned vals[32];
    unsigned s = 0;
    #pragma unroll
    for (int k = 0; k < 32; k++) { vals[k] = g_hist[t * 32 + k]; s += vals[k]; }
    sm[t] = s;
    __syncthreads();
    for (int off = 1; off < 1024; off <<= 1) {
        unsigned v = (t >= off) ? sm[t - off] : 0u;
        __syncthreads();
        sm[t] += v;
        __syncthreads();
    }
    unsigned run = sm[t] - s;            // exclusive prefix of this chunk
    #pragma unroll
    for (int k = 0; k < 32; k++) { g_hist[t * 32 + k] = run; run += vals[k]; }
}

__global__ void scatter_k(const float* __restrict__ x, int N) {
    int i = blockIdx.x * blockDim.x + threadIdx.x;
    if (i >= N) return;
    float x0 = x[3 * i + 0] * 0.5f + 0.5f;
    float x1 = x[3 * i + 1] * 0.5f + 0.5f;
    float x2 = x[3 * i + 2] * 0.5f + 0.5f;
    unsigned key = morton_key(x0, x1, x2);
    unsigned slot = atomicAdd(&g_hist[key], 1u);
    g_xs[slot] = make_float4(x0, x1, x2, 0.0f);
    g_perm[slot] = i;
}

// ---------------- main fused kernel ----------------

// packed fp32x2 FMA (full-precision fp32, 2 lanes per instruction)
__device__ __forceinline__ ull fma2u(ull a, ull b, ull c) {
    ull d;
    asm("fma.rn.f32x2 %0, %1, %2, %3;" : "=l"(d) : "l"(a), "l"(b), "l"(c));
    return d;
}
__device__ __forceinline__ ull pack2(float lo, float hi) {
    ull r;
    asm("mov.b64 %0, {%1, %2};" : "=l"(r) : "f"(lo), "f"(hi));
    return r;
}
__device__ __forceinline__ void unpack2(ull v, float& lo, float& hi) {
    asm("mov.b64 {%0, %1}, %2;" : "=f"(lo), "=f"(hi) : "l"(v));
}

// half-interleave: col n of a 64-wide row -> [low4|high4] per 32-byte group,
// so even lanes (offset +0) read neurons 4j..4j+3 and odd lanes (+16B) read
// 32+4j..32+4j+3 in the SAME LDS.128 issue slot, contiguous 32B, conflict-free.
__device__ __forceinline__ int ilv64(int n) {
    int half = n >> 5, cw = (n & 31) >> 2, w = n & 3;
    return cw * 8 + half * 4 + w;
}

__global__ __launch_bounds__(256, 2)
void hashgrid_mlp_kernel(const float2* __restrict__ tables,
                         const float*  __restrict__ resolutions,
                         const float*  __restrict__ W1, const float* __restrict__ b1,
                         const float*  __restrict__ W2, const float* __restrict__ b2,
                         const float*  __restrict__ W3, const float* __restrict__ b3,
                         float* __restrict__ out, int N)
{
    __shared__ __align__(16) float sW1[32 * 64];
    __shared__ __align__(16) float sW2[64 * 64];
    __shared__ __align__(16) float sB1[64];
    __shared__ __align__(16) float sB2[64];
    __shared__ __align__(16) float sW3[64];
    __shared__ __align__(16) float sRes[16];
    __shared__ float sB3;

    const int tid = threadIdx.x;
    for (int k = tid; k < 32 * 64; k += blockDim.x) {
        int r = k >> 6, n = k & 63;
        sW1[r * 64 + ilv64(n)] = W1[k];
    }
    for (int k = tid; k < 64 * 64; k += blockDim.x) {
        int r = k >> 6, n = k & 63;
        sW2[r * 64 + ilv64(n)] = W2[k];
    }
    if (tid < 64) { sB1[tid] = b1[tid]; sB2[tid] = b2[tid]; sW3[tid] = W3[tid]; }
    if (tid < 16) sRes[tid] = resolutions[tid];
    if (tid == 0) sB3 = b3[0];
    __syncthreads();

    const int gi = blockIdx.x * blockDim.x + tid;
    // clamp instead of early-return: keeps every warp fully active for shuffles
    const int i = gi < N ? gi : (N - 1);

    const unsigned psel = (unsigned)(tid & 1);   // 0: low neurons, 1: high
    const unsigned FULL = 0xffffffffu;

    const float4 xs = g_xs[i];           // sorted, already mapped to [0,1]
    const float x0 = xs.x, x1 = xs.y, x2 = xs.z;

    // h1 for the lane-pair's two points (A = even lane's, B = odd lane's),
    // restricted to this lane's neuron half: 16 f32x2 each.
    ull hA[16], hB[16];
    #pragma unroll
    for (int m = 0; m < 16; m++)
        hA[m] = hB[m] = ((const ull*)(sB1 + psel * 32))[m];

    // two-stage pipeline for the per-level gathers (unchanged from R5 best)
    float2   tbuf[2][8];
    float    wbuf[2][3];
    unsigned mbuf[2];

    auto issue = [&](int L, float2* tb, float* wb, unsigned& mb) {
        const float res = sRes[L];
        const float px = x0 * res, py = x1 * res, pz = x2 * res;
        const float fx = floorf(px), fy = floorf(py), fz = floorf(pz);
        wb[0] = px - fx; wb[1] = py - fy; wb[2] = pz - fz;
        const unsigned cx = (unsigned)fx, cy = (unsigned)fy, cz = (unsigned)fz;
        const unsigned hy0 = cy * PRIME_Y, hy1 = hy0 + PRIME_Y;
        const unsigned hz0 = cz * PRIME_Z, hz1 = hz0 + PRIME_Z;
        unsigned rr[4];
        rr[0] = hy0 ^ hz0; rr[1] = hy1 ^ hz0; rr[2] = hy0 ^ hz1; rr[3] = hy1 ^ hz1;
        const float2* __restrict__ base = tables + (size_t)L * TSIZE;
        unsigned m = 0;
        if (!(cx & 1u)) {
            #pragma unroll
            for (int j = 0; j < 4; j++) {
                const unsigned i0 = (cx ^ rr[j]) & TMASK;
                m |= (i0 & 1u) << j;
                const float4 v = __ldg((const float4*)(base + (i0 & ~1u)));
                tb[2 * j]     = make_float2(v.x, v.y);
                tb[2 * j + 1] = make_float2(v.z, v.w);
            }
        } else {
            #pragma unroll
            for (int j = 0; j < 4; j++) {
                const unsigned i0 = (cx        ^ rr[j]) & TMASK;
                const unsigned i1 = ((cx + 1u) ^ rr[j]) & TMASK;
                tb[2 * j]     = __ldg(base + i0);
                tb[2 * j + 1] = __ldg(base + i1);
            }
        }
        mb = m;
    };

    issue(0, tbuf[0], wbuf[0], mbuf[0]);

    #pragma unroll
    for (int L = 0; L < NLEV; L++) {
        const int cur = L & 1;
        if (L < NLEV - 1) issue(L + 1, tbuf[cur ^ 1], wbuf[cur ^ 1], mbuf[cur ^ 1]);

        // trilinear interpolation for level L
        const float wx1 = wbuf[cur][0], wy1 = wbuf[cur][1], wz1 = wbuf[cur][2];
        const float wx0 = 1.0f - wx1, wy0 = 1.0f - wy1, wz0 = 1.0f - wz1;
        float wyz[4];
        wyz[0] = wy0 * wz0; wyz[1] = wy1 * wz0; wyz[2] = wy0 * wz1; wyz[3] = wy1 * wz1;
        const float2* t = tbuf[cur];
        const unsigned m = mbuf[cur];
        float f0 = 0.0f, f1 = 0.0f;
        #pragma unroll
        for (int j = 0; j < 4; j++) {
            const bool  s  = (m >> j) & 1u;
            const float wl = s ? wx1 : wx0;
            const float wh = s ? wx0 : wx1;
            const float cl = wl * wyz[j], ch = wh * wyz[j];
            f0 += cl * t[2 * j].x + ch * t[2 * j + 1].x;
            f1 += cl * t[2 * j].y + ch * t[2 * j + 1].y;
        }

        // exchange features within the lane pair: both lanes get (f0,f1) of A and B
        const ull own = pack2(f0, f1);
        const ull oth = __shfl_xor_sync(FULL, own, 1);
        float f0A, f1A, f0B, f1B;
        unpack2(psel ? oth : own, f0A, f1A);
        unpack2(psel ? own : oth, f0B, f1B);
        const ull a0A = pack2(f0A, f0A), a1A = pack2(f1A, f1A);
        const ull a0B = pack2(f0B, f0B), a1B = pack2(f1B, f1B);

        // layer-1: each weight chunk loaded once per pair (lane-split halves)
        const float* r0 = sW1 + (2 * L) * 64 + psel * 4;       // feature-0 row
        const float* r1 = r0 + 64;                              // feature-1 row
        #pragma unroll
        for (int j = 0; j < 8; j++) {
            const ulonglong2 Wa = *(const ulonglong2*)(r0 + j * 8);
            hA[2 * j]     = fma2u(a0A, Wa.x, hA[2 * j]);
            hA[2 * j + 1] = fma2u(a0A, Wa.y, hA[2 * j + 1]);
            hB[2 * j]     = fma2u(a0B, Wa.x, hB[2 * j]);
            hB[2 * j + 1] = fma2u(a0B, Wa.y, hB[2 * j + 1]);
            const ulonglong2 Wb = *(const ulonglong2*)(r1 + j * 8);
            hA[2 * j]     = fma2u(a1A, Wb.x, hA[2 * j]);
            hA[2 * j + 1] = fma2u(a1A, Wb.y, hA[2 * j + 1]);
            hB[2 * j]     = fma2u(a1B, Wb.x, hB[2 * j]);
            hB[2 * j + 1] = fma2u(a1B, Wb.y, hB[2 * j + 1]);
        }
    }

    // ---- layer 2: pair-split. Each lane accumulates its neuron half for BOTH
    // points; activations exchanged via one shuffle per position p.
    ull accA[16], accB[16];
    #pragma unroll
    for (int m = 0; m < 16; m++)
        accA[m] = accB[m] = ((const ull*)(sB2 + psel * 32))[m];

    #pragma unroll
    for (int p = 0; p < 32; p++) {
        float t0, t1;
        unpack2(hA[p >> 1], t0, t1);
        float vA = (p & 1) ? t1 : t0;
        unpack2(hB[p >> 1], t0, t1);
        float vB = (p & 1) ? t1 : t0;
        vA = fmaxf(vA, 0.0f);
        vB = fmaxf(vB, 0.0f);
        const ull own = pack2(vA, vB);             // this lane's k-row values
        const ull oth = __shfl_xor_sync(FULL, own, 1);
        // even lane owns k = p, odd lane owns k = 32+p
        float vAl, vBl, vAh, vBh;
        unpack2(psel ? oth : own, vAl, vBl);       // k = p
        unpack2(psel ? own : oth, vAh, vBh);       // k = 32+p
        const ull aAl = pack2(vAl, vAl), aBl = pack2(vBl, vBl);
        const ull aAh = pack2(vAh, vAh), aBh = pack2(vBh, vBh);
        const float* rl = sW2 + p * 64 + psel * 4;
        const float* rh = sW2 + (32 + p) * 64 + psel * 4;
        #pragma unroll
        for (int j = 0; j < 8; j++) {
            const ulonglong2 Wl = *(const ulonglong2*)(rl + j * 8);
            accA[2 * j]     = fma2u(aAl, Wl.x, accA[2 * j]);
            accA[2 * j + 1] = fma2u(aAl, Wl.y, accA[2 * j + 1]);
            accB[2 * j]     = fma2u(aBl, Wl.x, accB[2 * j]);
            accB[2 * j + 1] = fma2u(aBl, Wl.y, accB[2 * j + 1]);
            const ulonglong2 Wh = *(const ulonglong2*)(rh + j * 8);
            accA[2 * j]     = fma2u(aAh, Wh.x, accA[2 * j]);
            accA[2 * j + 1] = fma2u(aAh, Wh.y, accA[2 * j + 1]);
            accB[2 * j]     = fma2u(aBh, Wh.x, accB[2 * j]);
            accB[2 * j + 1] = fma2u(aBh, Wh.y, accB[2 * j + 1]);
        }
    }

    // ---- layer 3: partial dot per lane-half, one shuffle to combine ----
    float pA = 0.0f, pB = 0.0f;
    #pragma unroll
    for (int m = 0; m < 16; m++) {
        float e0, e1;
        const float w30 = sW3[psel * 32 + 2 * m];
        const float w31 = sW3[psel * 32 + 2 * m + 1];
        unpack2(accA[m], e0, e1);
        pA += fmaxf(e0, 0.0f) * w30 + fmaxf(e1, 0.0f) * w31;
        unpack2(accB[m], e0, e1);
        pB += fmaxf(e0, 0.0f) * w30 + fmaxf(e1, 0.0f) * w31;
    }
    const ull ownp = pack2(pA, pB);
    const ull othp = __shfl_xor_sync(FULL, ownp, 1);
    float qA, qB;
    unpack2(othp, qA, qB);
    const float myout = psel ? (pB + qB + sB3) : (pA + qA + sB3);

    if (gi < N) out[g_perm[i]] = myout;   // route back to original order
}

extern "C" void kernel_launch(void* const* d_in, const int* in_sizes, int n_in,
                              void* d_out, int out_size)
{
    const float*  x    = (const float*) d_in[0];
    const float2* tabs = (const float2*)d_in[1];
    const float*  res  = (const float*) d_in[2];
    const float*  W1   = (const float*) d_in[3];
    const float*  b1   = (const float*) d_in[4];
    const float*  W2   = (const float*) d_in[5];
    const float*  b2   = (const float*) d_in[6];
    const float*  W3   = (const float*) d_in[7];
    const float*  b3   = (const float*) d_in[8];

    const int N = in_sizes[0] / 3;
    const int threads = 256;
    const int blocks = (N + threads - 1) / threads;

    // spatial binning presort (all graph-capturable kernel launches)
    zero_hist_k<<<(NBINS + 255) / 256, 256>>>();
    hist_k<<<blocks, threads>>>(x, N);
    scan_k<<<1, 1024>>>();
    scatter_k<<<blocks, threads>>>(x, N);

    hashgrid_mlp_kernel<<<blocks, threads>>>(tabs, res, W1, b1, W2, b2, W3, b3,
                                             (float*)d_out, N);
}